// round 2
// baseline (speedup 1.0000x reference)
#include <cuda_runtime.h>
#include <math.h>

// Spherization, per row r (512 features):
//   ang_j = A*sigmoid(s*x) + phiL,  A = PI_t - 2*phiL (PI_t = 3.141592 truncated)
//   out[k]   = radius * prod_{j<k}(sin(ang_j)+eps) * sgn(cos_k)*(|cos(ang_k)|+eps)
//   out[512] = radius * prod_j (sin(ang_j)+eps)
// Identity used: ang = PI_t/2 + halfA*u0, u0 = tanh(z/2) = (1-e^-z)/(1+e^-z).
// With delta = (pi_true - PI_t)/2 and u0' = u0 - delta/halfA:
//   sin(ang) = cos(halfA*u0'),  cos(ang) = -sin(halfA*u0')
// Both evaluated by 3/2-term Taylor polynomials in w=u0'^2 (|halfA*u0'|<=0.2313,
// max rel err 2e-10 / 3e-8). Only 2 MUFU per element (EX2, RCP).

#define NFEAT 512
#define ROW_OUT 513
#define SROW_PITCH 520
#define WARPS_PER_BLOCK 8
#define EPSf 1e-6f

__global__ __launch_bounds__(WARPS_PER_BLOCK * 32)
void spherization_kernel(const float* __restrict__ x,
                         const float* __restrict__ scaling_p,
                         const float* __restrict__ radius_p,
                         float* __restrict__ out,
                         int nrows,
                         float C3, float C2, float C1,      // cos(halfA*u) poly coeffs in w
                         float S2, float S1, float S0,      // halfA-scaled sin poly coeffs
                         float D2)                          // delta/halfA
{
    __shared__ float sbuf[WARPS_PER_BLOCK * SROW_PITCH];

    const int wib  = threadIdx.x >> 5;
    const int lane = threadIdx.x & 31;
    const int row  = blockIdx.x * WARPS_PER_BLOCK + wib;
    if (row >= nrows) return;

    const float scaling = __ldg(scaling_p);
    const float radius  = __ldg(radius_p);
    const float cmul = -scaling * 1.4426950408889634f;   // t = x*cmul -> e = 2^t = e^{-z}

    const float4* xr = reinterpret_cast<const float4*>(x + (size_t)row * NFEAT);
    float* srow = sbuf + wib * SROW_PITCH;

    // prefetch all loads (MLP=4)
    float4 v[4];
    #pragma unroll
    for (int j = 0; j < 4; j++) v[j] = xr[lane + 32 * j];

    float carryN = -radius;   // negative carry absorbs the -sin(u) sign of cos(ang)

    #pragma unroll
    for (int j = 0; j < 4; j++) {
        float vv[4] = {v[j].x, v[j].y, v[j].z, v[j].w};
        float sv[4], cvp[4];
        #pragma unroll
        for (int m = 0; m < 4; m++) {
            float t  = fminf(vv[m] * cmul, 80.0f);       // clamp: avoid e=inf -> NaN
            float e;  asm("ex2.approx.f32 %0, %1;" : "=f"(e) : "f"(t));
            float d  = e + 1.0f;
            float g  = 1.0f - e;
            float r;  asm("rcp.approx.f32 %0, %1;" : "=f"(r) : "f"(d));
            float u0 = fmaf(g, r, -D2);                  // tanh(z/2) - delta/halfA
            float w  = u0 * u0;
            // sin(ang)+eps = cos(halfA*u0') + eps
            sv[m] = fmaf(fmaf(fmaf(C3, w, C2), w, C1), w, 1.0f + EPSf);
            // cos(ang) = -sin(halfA*u0');  cvp = sin + copysign(eps,u0); cv = -cvp
            float p  = fmaf(fmaf(S2, w, S1), w, S0);
            cvp[m] = fmaf(u0, p, copysignf(EPSf, u0));
        }
        // local exclusive prefixes
        float e1  = sv[0];
        float e2  = e1 * sv[1];
        float e3  = e2 * sv[2];
        float tot = e3 * sv[3];

        // warp-inclusive scan of per-lane totals
        float incl = tot;
        #pragma unroll
        for (int d = 1; d < 32; d <<= 1) {
            float t2 = __shfl_up_sync(0xFFFFFFFFu, incl, d);
            if (lane >= d) incl *= t2;
        }
        float excl = __shfl_up_sync(0xFFFFFFFFu, incl, 1);
        if (lane == 0) excl = 1.0f;

        float bpN = carryN * excl;   // = -(radius * prod of everything before this lane)

        float4 o;
        o.x = bpN * cvp[0];
        o.y = (bpN * e1) * cvp[1];
        o.z = (bpN * e2) * cvp[2];
        o.w = (bpN * e3) * cvp[3];
        reinterpret_cast<float4*>(srow)[lane + 32 * j] = o;

        carryN *= __shfl_sync(0xFFFFFFFFu, incl, 31);
    }
    if (lane == 0) srow[NFEAT] = -carryN;   // out[512] = radius * full product
    __syncwarp();

    // coalesced copy SMEM row -> GMEM (row pitch 513)
    float* orow = out + (size_t)row * ROW_OUT;
    #pragma unroll
    for (int it = 0; it < 16; it++)
        orow[lane + 32 * it] = srow[lane + 32 * it];
    if (lane == 0) orow[NFEAT] = srow[NFEAT];
}

extern "C" void kernel_launch(void* const* d_in, const int* in_sizes, int n_in,
                              void* d_out, int out_size)
{
    int xi = 0;
    for (int i = 0; i < n_in; i++) if (in_sizes[i] > in_sizes[xi]) xi = i;
    int others[2]; int no = 0;
    for (int i = 0; i < n_in && no < 2; i++) if (i != xi) others[no++] = i;

    const float* x   = (const float*)d_in[xi];
    const float* sc  = (const float*)d_in[others[0]];
    const float* rad = (const float*)d_in[others[1]];

    float* out = (float*)d_out;
    int nrows = in_sizes[xi] / NFEAT;

    // constants in double; PI truncated exactly as in the reference
    const double PI_d = 3.141592;
    double phiL = asin(pow(1e-6, 1.0 / 512.0));
    double phiU = PI_d / 2.0 * (1.0 - 0.01);
    if (phiU < phiL) phiL = phiU;
    double A     = PI_d - 2.0 * phiL;
    double halfA = 0.5 * A;
    double h     = halfA * halfA;
    // cos(halfA*u) = 1 - h/2 w + h^2/24 w^2 - h^3/720 w^3   (w = u^2)
    float C1 = (float)(-h / 2.0);
    float C2 = (float)(h * h / 24.0);
    float C3 = (float)(-h * h * h / 720.0);
    // sin(halfA*u) = u * (halfA - halfA^3/6 w + halfA^5/120 w^2)
    float S0 = (float)(halfA);
    float S1 = (float)(-halfA * h / 6.0);
    float S2 = (float)(halfA * h * h / 120.0);
    // truncated-pi correction: ang - pi_true/2 = halfA*(u0 - D2)
    double delta = (3.14159265358979323846 - PI_d) * 0.5;
    float D2 = (float)(delta / halfA);

    int blocks = (nrows + WARPS_PER_BLOCK - 1) / WARPS_PER_BLOCK;
    spherization_kernel<<<blocks, WARPS_PER_BLOCK * 32>>>(
        x, sc, rad, out, nrows, C3, C2, C1, S2, S1, S0, D2);
}

// round 3
// speedup vs baseline: 1.0904x; 1.0904x over previous
#include <cuda_runtime.h>
#include <math.h>

// Spherization, per row r (512 features):
//   ang_j = A*sigmoid(scaling*x) + phiL
//   out[k]   = radius * prod_{j<k}(sin(ang_j)+eps) * sgn(cos_k)*(|cos(ang_k)|+eps)
//   out[512] = radius * prod_j (sin(ang_j)+eps)
// R1 pipeline (EX2+RCP sigmoid, MUFU.SIN/COS — accuracy 2e-6) with issue-slot cuts:
// folded exp constant, copysign-eps cos sign, LDS.64 readback.
// One warp per row; lane owns elements 128j+4l+m; 4 chained warp scans.

#define NFEAT 512
#define ROW_OUT 513
#define SROW_PITCH 520   // even -> 8B-aligned float2 rows
#define WARPS_PER_BLOCK 8
#define EPSf 1e-6f

__global__ __launch_bounds__(WARPS_PER_BLOCK * 32)
void spherization_kernel(const float* __restrict__ x,
                         const float* __restrict__ scaling_p,
                         const float* __restrict__ radius_p,
                         float* __restrict__ out,
                         int nrows, float A, float phiL)
{
    __shared__ float sbuf[WARPS_PER_BLOCK * SROW_PITCH];

    const int wib  = threadIdx.x >> 5;
    const int lane = threadIdx.x & 31;
    const int row  = blockIdx.x * WARPS_PER_BLOCK + wib;
    if (row >= nrows) return;

    const float scaling = __ldg(scaling_p);
    const float radius  = __ldg(radius_p);
    // e = exp(-scaling*x) = 2^(x * cmul)
    const float cmul = -scaling * 1.4426950408889634f;

    const float4* xr = reinterpret_cast<const float4*>(x + (size_t)row * NFEAT);
    float* srow = sbuf + wib * SROW_PITCH;

    // prefetch all loads (MLP=4)
    float4 v[4];
    #pragma unroll
    for (int j = 0; j < 4; j++) v[j] = xr[lane + 32 * j];

    float carry = radius;

    #pragma unroll
    for (int j = 0; j < 4; j++) {
        float vv[4] = {v[j].x, v[j].y, v[j].z, v[j].w};
        float sv[4], cv[4];
        #pragma unroll
        for (int m = 0; m < 4; m++) {
            float t = vv[m] * cmul;
            float e;  asm("ex2.approx.f32 %0, %1;" : "=f"(e) : "f"(t));   // e=inf ok
            float d = e + 1.0f;
            float r;  asm("rcp.approx.f32 %0, %1;" : "=f"(r) : "f"(d));   // sigmoid
            float ang = fmaf(A, r, phiL);            // in [phiL, pi - phiL]
            float sn  = __sinf(ang);                 // > 0 on range
            float cs  = __cosf(ang);
            sv[m] = sn + EPSf;
            cv[m] = cs + copysignf(EPSf, cs);        // sign(cs)*(|cs|+eps)
        }
        // local exclusive prefixes within the 4 owned elements
        float e1  = sv[0];
        float e2  = e1 * sv[1];
        float e3  = e2 * sv[2];
        float tot = e3 * sv[3];

        // warp-inclusive scan of per-lane block totals
        float incl = tot;
        #pragma unroll
        for (int d = 1; d < 32; d <<= 1) {
            float t2 = __shfl_up_sync(0xFFFFFFFFu, incl, d);
            if (lane >= d) incl *= t2;
        }
        float excl = __shfl_up_sync(0xFFFFFFFFu, incl, 1);
        if (lane == 0) excl = 1.0f;

        float bp = carry * excl;   // radius * prod of everything before this lane

        float4 o;
        o.x = bp * cv[0];
        o.y = (bp * e1) * cv[1];
        o.z = (bp * e2) * cv[2];
        o.w = (bp * e3) * cv[3];
        reinterpret_cast<float4*>(srow)[lane + 32 * j] = o;

        carry *= __shfl_sync(0xFFFFFFFFu, incl, 31);
    }
    if (lane == 0) srow[NFEAT] = carry;   // out[512] = radius * full product
    __syncwarp();

    // coalesced copy SMEM row -> GMEM: float2 reads, dense scalar writes
    float* orow = out + (size_t)row * ROW_OUT;
    const float2* srow2 = reinterpret_cast<const float2*>(srow);
    #pragma unroll
    for (int it = 0; it < 8; it++) {
        float2 p = srow2[lane + 32 * it];             // elements 2k, 2k+1
        int k2 = 2 * (lane + 32 * it);
        orow[k2]     = p.x;
        orow[k2 + 1] = p.y;
    }
    if (lane == 0) orow[NFEAT] = srow[NFEAT];
}

extern "C" void kernel_launch(void* const* d_in, const int* in_sizes, int n_in,
                              void* d_out, int out_size)
{
    int xi = 0;
    for (int i = 0; i < n_in; i++) if (in_sizes[i] > in_sizes[xi]) xi = i;
    int others[2]; int no = 0;
    for (int i = 0; i < n_in && no < 2; i++) if (i != xi) others[no++] = i;

    const float* x   = (const float*)d_in[xi];
    const float* sc  = (const float*)d_in[others[0]];   // scaling
    const float* rad = (const float*)d_in[others[1]];   // radius

    float* out = (float*)d_out;
    int nrows = in_sizes[xi] / NFEAT;

    // constants in double; PI truncated exactly as in the reference
    const double PI_d = 3.141592;
    double phiL = asin(pow(1e-6, 1.0 / 512.0));
    double phiU = PI_d / 2.0 * (1.0 - 0.01);
    if (phiU < phiL) phiL = phiU;
    float A = (float)(PI_d - 2.0 * phiL);

    int blocks = (nrows + WARPS_PER_BLOCK - 1) / WARPS_PER_BLOCK;
    spherization_kernel<<<blocks, WARPS_PER_BLOCK * 32>>>(
        x, sc, rad, out, nrows, A, (float)phiL);
}